// round 1
// baseline (speedup 1.0000x reference)
#include <cuda_runtime.h>
#include <math.h>

#define NB 32
#define HW 16384

// Per-b Fourier coefficients of ev(x0,x1):
// [0]   : c00 (real)        [1] pad
// [2..7]: q_n = 2*c_{0,n}, n=1..3 (complex)
// [8..49]: t_{m,n} = 2*c_{m,n}, m=1..3, n=-3..3 (21 complex)
__device__ __align__(16) float g_coef[NB][52];

__device__ __forceinline__ float2 cmul(float2 a, float2 b) {
    return make_float2(fmaf(a.x, b.x, -a.y * b.y), fmaf(a.x, b.y, a.y * b.x));
}
__device__ __forceinline__ float2 cfma(float2 a, float2 b, float2 c) {
    c.x = fmaf(a.x, b.x, fmaf(-a.y, b.y, c.x));
    c.y = fmaf(a.x, b.y, fmaf(a.y, b.x, c.y));
    return c;
}

// ---------------------------------------------------------------------------
// Setup: build ansatz-block matrices per b, sample ev on 7x7 grid, exact DFT.
// ---------------------------------------------------------------------------
__global__ void setup_kernel(const float* __restrict__ qstyles) {
    const int b = blockIdx.x;
    const int t = threadIdx.x;
    __shared__ float sh_ev[49];

    // Every thread builds all four 4x4 block matrices (redundant but trivial).
    float2 M[4][16];
#pragma unroll
    for (int blk = 0; blk < 4; ++blk) {
        float2* Mb = M[blk];
        for (int i = 0; i < 16; ++i)
            Mb[i] = make_float2((i % 5) == 0 ? 1.f : 0.f, 0.f);
        for (int j = 0; j < 2; ++j) {           // ANSATZ layers
            for (int k = 0; k < 2; ++k) {       // wires
                const float* p = qstyles + ((((b * 4 + blk) * 2 + j) * 2 + k) * 3);
                float th = p[0], ph = p[1], la = p[2];
                float ct = cosf(0.5f * th), st = sinf(0.5f * th);
                float cl = cosf(la), sl = sinf(la);
                float cp = cosf(ph), sp = sinf(ph);
                float cpl = cosf(ph + la), spl = sinf(ph + la);
                float2 u00 = make_float2(ct, 0.f);
                float2 u01 = make_float2(-cl * st, -sl * st);
                float2 u10 = make_float2(cp * st, sp * st);
                float2 u11 = make_float2(cpl * ct, spl * ct);
                if (k == 0) {
                    // wire 0 = most significant bit: row pairs (r, r+2)
                    for (int c = 0; c < 4; ++c)
                        for (int r = 0; r < 2; ++r) {
                            float2 a = Mb[(r + 0) * 4 + c];
                            float2 d = Mb[(r + 2) * 4 + c];
                            Mb[(r + 0) * 4 + c] = cfma(u00, a, cmul(u01, d));
                            Mb[(r + 2) * 4 + c] = cfma(u10, a, cmul(u11, d));
                        }
                } else {
                    // wire 1 = least significant bit: row pairs (r, r+1)
                    for (int c = 0; c < 4; ++c)
                        for (int r = 0; r < 4; r += 2) {
                            float2 a = Mb[(r + 0) * 4 + c];
                            float2 d = Mb[(r + 1) * 4 + c];
                            Mb[(r + 0) * 4 + c] = cfma(u00, a, cmul(u01, d));
                            Mb[(r + 1) * 4 + c] = cfma(u10, a, cmul(u11, d));
                        }
                }
            }
            // CNOT(ctrl=wire0 -> tgt=wire1): swap rows 2 and 3
            for (int c = 0; c < 4; ++c) {
                float2 tmp = Mb[2 * 4 + c];
                Mb[2 * 4 + c] = Mb[3 * 4 + c];
                Mb[3 * 4 + c] = tmp;
            }
        }
    }

    const float TWO_PI_7 = 6.28318530717958647692f / 7.0f;

    if (t < 49) {
        int j = t / 7, kk = t % 7;
        float x0 = TWO_PI_7 * (float)j, x1 = TWO_PI_7 * (float)kk;
        float ca, sa, cb, sb;
        sincosf(0.5f * (x0 + x1), &sa, &ca);
        sincosf(0.5f * (x0 - x1), &sb, &cb);
        float2 d0 = make_float2(ca, -sa), d1 = make_float2(cb, -sb);
        float2 d2 = make_float2(cb, sb), d3 = make_float2(ca, sa);
        float2 s[4];
        for (int i = 0; i < 4; ++i) s[i] = M[0][i * 4 + 0];  // A0 |00>
        for (int it = 1; it <= 3; ++it) {
            float2 tv[4];
            tv[0] = cmul(d0, s[0]); tv[1] = cmul(d1, s[1]);
            tv[2] = cmul(d2, s[2]); tv[3] = cmul(d3, s[3]);
            for (int i = 0; i < 4; ++i) {
                float2 acc = cmul(M[it][i * 4 + 0], tv[0]);
                for (int kx = 1; kx < 4; ++kx)
                    acc = cfma(M[it][i * 4 + kx], tv[kx], acc);
                s[i] = acc;
            }
        }
        float ev = (s[0].x * s[0].x + s[0].y * s[0].y)
                 + (s[1].x * s[1].x + s[1].y * s[1].y)
                 - (s[2].x * s[2].x + s[2].y * s[2].y)
                 - (s[3].x * s[3].x + s[3].y * s[3].y);
        sh_ev[t] = ev;
    }
    __syncthreads();

    if (t < 25) {
        int m, n;
        if (t < 4) { m = 0; n = t; }
        else       { m = 1 + (t - 4) / 7; n = ((t - 4) % 7) - 3; }
        float cr = 0.f, ci = 0.f;
        for (int j = 0; j < 7; ++j)
            for (int kk = 0; kk < 7; ++kk) {
                float ang = -TWO_PI_7 * (float)(m * j + n * kk);
                float sn, cs;
                sincosf(ang, &sn, &cs);
                float e = sh_ev[j * 7 + kk];
                cr = fmaf(e, cs, cr);
                ci = fmaf(e, sn, ci);
            }
        cr *= (1.f / 49.f);
        ci *= (1.f / 49.f);
        float* g = g_coef[b];
        if (m == 0 && n == 0) {
            g[0] = cr;
            g[1] = 0.f;
        } else if (m == 0) {
            g[2 + 2 * (n - 1)] = 2.f * cr;
            g[3 + 2 * (n - 1)] = 2.f * ci;
        } else {
            int off = 8 + 2 * ((m - 1) * 7 + (n + 3));
            g[off] = 2.f * cr;
            g[off + 1] = 2.f * ci;
        }
    }
}

// ---------------------------------------------------------------------------
// Main: ev = c00 + sum_n Re(q_n z^n) + sum_{m=1..3} Re(w^m * sum_n t_{mn} z^n)
// ---------------------------------------------------------------------------
__global__ void __launch_bounds__(256) qlayer_kernel(const float* __restrict__ x,
                                                     float* __restrict__ out) {
    const int b = blockIdx.y;
    const float* g = g_coef[b];
    const float2* g2 = reinterpret_cast<const float2*>(g);

    float r00 = g[0];
    float2 q[3], tc[21];
#pragma unroll
    for (int i = 0; i < 3; ++i) q[i] = g2[1 + i];
#pragma unroll
    for (int i = 0; i < 21; ++i) tc[i] = g2[4 + i];

    const float2* xin = reinterpret_cast<const float2*>(x) + (size_t)b * HW;
    float* o = out + (size_t)b * HW;

    for (int e = blockIdx.x * blockDim.x + threadIdx.x; e < HW;
         e += blockDim.x * gridDim.x) {
        float2 xv = xin[e];
        float s0v, c0v, s1v, c1v;
        __sincosf(xv.x, &s0v, &c0v);
        __sincosf(xv.y, &s1v, &c1v);

        float2 w1 = make_float2(c0v, s0v);
        float2 z1 = make_float2(c1v, s1v);
        float2 w2 = make_float2(fmaf(c0v, c0v, -s0v * s0v), 2.f * c0v * s0v);
        float2 z2 = make_float2(fmaf(c1v, c1v, -s1v * s1v), 2.f * c1v * s1v);
        float2 w3 = cmul(w2, w1);
        float2 z3 = cmul(z2, z1);

        float2 zp[7];
        zp[0] = make_float2(z3.x, -z3.y);
        zp[1] = make_float2(z2.x, -z2.y);
        zp[2] = make_float2(z1.x, -z1.y);
        zp[3] = make_float2(1.f, 0.f);
        zp[4] = z1; zp[5] = z2; zp[6] = z3;

        float ev = r00;
        ev += q[0].x * z1.x - q[0].y * z1.y;
        ev += q[1].x * z2.x - q[1].y * z2.y;
        ev += q[2].x * z3.x - q[2].y * z3.y;

        float2 wm[3] = {w1, w2, w3};
#pragma unroll
        for (int m = 0; m < 3; ++m) {
            float2 h = tc[m * 7 + 3];  // n = 0 term (z^0 = 1)
#pragma unroll
            for (int n = 0; n < 7; ++n) {
                if (n == 3) continue;
                h = cfma(tc[m * 7 + n], zp[n], h);
            }
            ev += wm[m].x * h.x - wm[m].y * h.y;
        }
        o[e] = ev;
    }
}

extern "C" void kernel_launch(void* const* d_in, const int* in_sizes, int n_in,
                              void* d_out, int out_size) {
    const float* x  = (const float*)d_in[0];
    const float* qs = (const float*)d_in[1];
    // Defensive: identify inputs by size (x has 1048576 elems, qstyles 1152)
    if (n_in >= 2 && in_sizes[0] < in_sizes[1]) {
        x  = (const float*)d_in[1];
        qs = (const float*)d_in[0];
    }

    setup_kernel<<<NB, 64>>>(qs);

    dim3 grid(16, NB);
    qlayer_kernel<<<grid, 256>>>(x, (float*)d_out);
}

// round 2
// speedup vs baseline: 2.2059x; 2.2059x over previous
#include <cuda_runtime.h>
#include <math.h>

#define NB 32
#define HW 16384

// Per-b coefficients, real trig-poly basis (56 floats):
// [0] c00  [1] pad
// [2..7]  qr1,qi1,qr2,qi2,qr3,qi3             (m=0, n=1..3; factor 2 baked in)
// for m=1..3 at off = 8+16*(m-1):
//   [off+0] t0r  [off+1] t0i  [off+2..3] pad  (t_{m,0} = 2 c_{m,0})
//   [off+4n .. off+4n+3] = Pr, Mi, Pi, Mr  for n=1..3
//   where P = 2(c_{m,n}+c_{m,-n}),  M = 2(c_{m,n}-c_{m,-n})
__device__ __align__(16) float g_coef[NB][56];

__device__ __forceinline__ float2 cmul(float2 a, float2 b) {
    return make_float2(fmaf(a.x, b.x, -a.y * b.y), fmaf(a.x, b.y, a.y * b.x));
}
__device__ __forceinline__ float2 cfma(float2 a, float2 b, float2 c) {
    c.x = fmaf(a.x, b.x, fmaf(-a.y, b.y, c.x));
    c.y = fmaf(a.x, b.y, fmaf(a.y, b.x, c.y));
    return c;
}

// ---------------------------------------------------------------------------
// Setup: 32 blocks (one per b), 64 threads. Matrices built once into smem,
// 49 grid evals in parallel, exact 7x7 DFT with precomputed twiddles.
// ---------------------------------------------------------------------------
__global__ void setup_kernel(const float* __restrict__ qstyles) {
    const int b = blockIdx.x;
    const int t = threadIdx.x;
    __shared__ float2 shM[4][16];
    __shared__ float sh_ev[49];
    __shared__ float2 tw[7];
    __shared__ float2 sh_c[4][7];

    const float TWO_PI_7 = 6.28318530717958647692f / 7.0f;

    // Phase 1a: threads 0..3 each build one 4x4 block matrix.
    if (t < 4) {
        const int blk = t;
        float2 Mb[16];
        for (int i = 0; i < 16; ++i)
            Mb[i] = make_float2((i % 5) == 0 ? 1.f : 0.f, 0.f);
        for (int j = 0; j < 2; ++j) {
            for (int k = 0; k < 2; ++k) {
                const float* p = qstyles + ((((b * 4 + blk) * 2 + j) * 2 + k) * 3);
                float th = p[0], ph = p[1], la = p[2];
                float ct, st, cl, sl, cp, sp, cpl, spl;
                sincosf(0.5f * th, &st, &ct);
                sincosf(la, &sl, &cl);
                sincosf(ph, &sp, &cp);
                sincosf(ph + la, &spl, &cpl);
                float2 u00 = make_float2(ct, 0.f);
                float2 u01 = make_float2(-cl * st, -sl * st);
                float2 u10 = make_float2(cp * st, sp * st);
                float2 u11 = make_float2(cpl * ct, spl * ct);
                if (k == 0) {
                    for (int c = 0; c < 4; ++c)
                        for (int r = 0; r < 2; ++r) {
                            float2 a = Mb[(r + 0) * 4 + c];
                            float2 d = Mb[(r + 2) * 4 + c];
                            Mb[(r + 0) * 4 + c] = cfma(u00, a, cmul(u01, d));
                            Mb[(r + 2) * 4 + c] = cfma(u10, a, cmul(u11, d));
                        }
                } else {
                    for (int c = 0; c < 4; ++c)
                        for (int r = 0; r < 4; r += 2) {
                            float2 a = Mb[(r + 0) * 4 + c];
                            float2 d = Mb[(r + 1) * 4 + c];
                            Mb[(r + 0) * 4 + c] = cfma(u00, a, cmul(u01, d));
                            Mb[(r + 1) * 4 + c] = cfma(u10, a, cmul(u11, d));
                        }
                }
            }
            for (int c = 0; c < 4; ++c) {  // CNOT: swap rows 2,3
                float2 tmp = Mb[2 * 4 + c];
                Mb[2 * 4 + c] = Mb[3 * 4 + c];
                Mb[3 * 4 + c] = tmp;
            }
        }
        for (int i = 0; i < 16; ++i) shM[blk][i] = Mb[i];
    }
    // Phase 1b: twiddles exp(-2*pi*i*k/7)
    if (t >= 8 && t < 15) {
        int k = t - 8;
        float sn, cs;
        sincosf(-TWO_PI_7 * (float)k, &sn, &cs);
        tw[k] = make_float2(cs, sn);
    }
    __syncthreads();

    // Phase 2: evaluate ev on 7x7 grid
    if (t < 49) {
        int j = t / 7, kk = t % 7;
        float x0 = TWO_PI_7 * (float)j, x1 = TWO_PI_7 * (float)kk;
        float ca, sa, cb, sb;
        sincosf(0.5f * (x0 + x1), &sa, &ca);
        sincosf(0.5f * (x0 - x1), &sb, &cb);
        float2 d0 = make_float2(ca, -sa), d1 = make_float2(cb, -sb);
        float2 d2 = make_float2(cb, sb), d3 = make_float2(ca, sa);
        float2 s[4];
        for (int i = 0; i < 4; ++i) s[i] = shM[0][i * 4 + 0];
        for (int it = 1; it <= 3; ++it) {
            float2 tv[4];
            tv[0] = cmul(d0, s[0]); tv[1] = cmul(d1, s[1]);
            tv[2] = cmul(d2, s[2]); tv[3] = cmul(d3, s[3]);
            for (int i = 0; i < 4; ++i) {
                float2 acc = cmul(shM[it][i * 4 + 0], tv[0]);
                for (int kx = 1; kx < 4; ++kx)
                    acc = cfma(shM[it][i * 4 + kx], tv[kx], acc);
                s[i] = acc;
            }
        }
        sh_ev[t] = (s[0].x * s[0].x + s[0].y * s[0].y)
                 + (s[1].x * s[1].x + s[1].y * s[1].y)
                 - (s[2].x * s[2].x + s[2].y * s[2].y)
                 - (s[3].x * s[3].x + s[3].y * s[3].y);
    }
    __syncthreads();

    // Phase 3: DFT -> raw coefficients c_{m,n}, m=0..3, n=-3..3
    if (t < 25) {
        int m, n;
        if (t < 4) { m = 0; n = t; }
        else       { m = 1 + (t - 4) / 7; n = ((t - 4) % 7) - 3; }
        float cr = 0.f, ci = 0.f;
        for (int j = 0; j < 7; ++j)
            for (int kk = 0; kk < 7; ++kk) {
                int r = (m * j + n * kk + 42) % 7;
                float e = sh_ev[j * 7 + kk];
                cr = fmaf(e, tw[r].x, cr);
                ci = fmaf(e, tw[r].y, ci);
            }
        sh_c[m][n + 3] = make_float2(cr * (1.f / 49.f), ci * (1.f / 49.f));
    }
    __syncthreads();

    // Phase 4: pack final layout
    float* g = g_coef[b];
    if (t == 15) { g[0] = sh_c[0][3].x; g[1] = 0.f; }
    if (t < 3) {
        int n = t + 1;
        g[2 + 2 * t] = 2.f * sh_c[0][3 + n].x;
        g[3 + 2 * t] = 2.f * sh_c[0][3 + n].y;
    }
    if (t >= 3 && t < 6) {
        int m = t - 2;
        int off = 8 + 16 * (m - 1);
        g[off + 0] = 2.f * sh_c[m][3].x;
        g[off + 1] = 2.f * sh_c[m][3].y;
        g[off + 2] = 0.f; g[off + 3] = 0.f;
    }
    if (t >= 6 && t < 15) {
        int p = t - 6;
        int m = 1 + p / 3, n = 1 + p % 3;
        int off = 8 + 16 * (m - 1) + 4 * n;
        float2 cp = sh_c[m][3 + n], cm = sh_c[m][3 - n];
        g[off + 0] = 2.f * (cp.x + cm.x);   // Pr
        g[off + 1] = 2.f * (cp.y - cm.y);   // Mi
        g[off + 2] = 2.f * (cp.y + cm.y);   // Pi
        g[off + 3] = 2.f * (cp.x - cm.x);   // Mr
    }
}

// ---------------------------------------------------------------------------
// Main: real trig-poly evaluation, 2 elements/thread, fully unrolled.
// ---------------------------------------------------------------------------
__device__ __forceinline__ float eval_elem(float x0, float x1,
                                           float c00,
                                           const float* qc,     // 6
                                           const float* tm) {   // 48 (3 blocks of 16)
    float s0, c0, s1, c1;
    __sincosf(x0, &s0, &c0);
    __sincosf(x1, &s1, &c1);

    // Chebyshev multiples
    float tc0 = c0 + c0;
    float cw1 = c0,                 sw1 = s0;
    float cw2 = fmaf(tc0, c0, -1.f), sw2 = tc0 * s0;
    float cw3 = fmaf(tc0, cw2, -c0), sw3 = fmaf(tc0, sw2, -s0);
    float tc1 = c1 + c1;
    float cz1 = c1,                 sz1 = s1;
    float cz2 = fmaf(tc1, c1, -1.f), sz2 = tc1 * s1;
    float cz3 = fmaf(tc1, cz2, -c1), sz3 = fmaf(tc1, sz2, -s1);

    float czn[3] = {cz1, cz2, cz3};
    float szn[3] = {sz1, sz2, sz3};
    float cwn[3] = {cw1, cw2, cw3};
    float swn[3] = {sw1, sw2, sw3};

    float ev = c00;
#pragma unroll
    for (int n = 0; n < 3; ++n) {
        ev = fmaf(qc[2 * n + 0], czn[n], ev);
        ev = fmaf(-qc[2 * n + 1], szn[n], ev);
    }
#pragma unroll
    for (int m = 0; m < 3; ++m) {
        const float* tb = tm + 16 * m;
        float hx = tb[0], hy = tb[1];
#pragma unroll
        for (int n = 0; n < 3; ++n) {
            const float* q4 = tb + 4 * (n + 1);  // Pr, Mi, Pi, Mr
            hx = fmaf(q4[0], czn[n], hx);
            hx = fmaf(-q4[1], szn[n], hx);
            hy = fmaf(q4[2], czn[n], hy);
            hy = fmaf(q4[3], szn[n], hy);
        }
        ev = fmaf(cwn[m], hx, ev);
        ev = fmaf(-swn[m], hy, ev);
    }
    return ev;
}

__global__ void __launch_bounds__(128) qlayer_kernel(const float* __restrict__ x,
                                                     float* __restrict__ out) {
    const int b = blockIdx.y;
    const float* g = g_coef[b];

    // Load 56 coefficient floats into registers (compiler vectorizes).
    float c00 = g[0];
    float qc[6];
#pragma unroll
    for (int i = 0; i < 6; ++i) qc[i] = g[2 + i];
    float tm[48];
#pragma unroll
    for (int i = 0; i < 48; ++i) tm[i] = g[8 + i];

    const int idx = blockIdx.x * 128 + threadIdx.x;   // pair index within b
    const float4 xv = reinterpret_cast<const float4*>(x)[(size_t)b * (HW / 2) + idx];

    float e0 = eval_elem(xv.x, xv.y, c00, qc, tm);
    float e1 = eval_elem(xv.z, xv.w, c00, qc, tm);

    reinterpret_cast<float2*>(out)[(size_t)b * (HW / 2) + idx] = make_float2(e0, e1);
}

extern "C" void kernel_launch(void* const* d_in, const int* in_sizes, int n_in,
                              void* d_out, int out_size) {
    const float* x  = (const float*)d_in[0];
    const float* qs = (const float*)d_in[1];
    if (n_in >= 2 && in_sizes[0] < in_sizes[1]) {
        x  = (const float*)d_in[1];
        qs = (const float*)d_in[0];
    }

    setup_kernel<<<NB, 64>>>(qs);

    dim3 grid(HW / (128 * 2), NB);   // (64, 32)
    qlayer_kernel<<<grid, 128>>>(x, (float*)d_out);
}

// round 3
// speedup vs baseline: 2.8037x; 1.2710x over previous
#include <cuda_runtime.h>
#include <math.h>

#define NB 32
#define HW 16384

// Packed, sign-baked coefficients: 50 u64 slots = 100 floats per b, each value
// duplicated in both halves for f32x2 broadcast.
// u64 layout:
//  [0]              c00
//  [1+2(n-1)]       qr_n      [2+2(n-1)]  -qi_n          (n=1..3)
//  base=7+14(m-1):
//  [base] t0r   [base+1] t0i
//  [base+2+4(n-1)+{0,1,2,3}] = Pr, -Mi, Pi, Mr           (n=1..3)
//  [49] pad
__device__ __align__(16) float g_coef_pk[NB][100];

typedef unsigned long long u64;

__device__ __forceinline__ u64 fma2(u64 a, u64 b, u64 c) {
    u64 d;
    asm("fma.rn.f32x2 %0, %1, %2, %3;" : "=l"(d) : "l"(a), "l"(b), "l"(c));
    return d;
}
__device__ __forceinline__ u64 mul2(u64 a, u64 b) {
    u64 d;
    asm("mul.rn.f32x2 %0, %1, %2;" : "=l"(d) : "l"(a), "l"(b));
    return d;
}
__device__ __forceinline__ u64 add2(u64 a, u64 b) {
    u64 d;
    asm("add.rn.f32x2 %0, %1, %2;" : "=l"(d) : "l"(a), "l"(b));
    return d;
}
__device__ __forceinline__ u64 neg2(u64 a) { return a ^ 0x8000000080000000ull; }
__device__ __forceinline__ u64 pk(float lo, float hi) {
    u64 d;
    asm("mov.b64 %0, {%1, %2};" : "=l"(d) : "f"(lo), "f"(hi));
    return d;
}

__device__ __forceinline__ float2 cmulc(float2 a, float2 b) {
    return make_float2(fmaf(a.x, b.x, -a.y * b.y), fmaf(a.x, b.y, a.y * b.x));
}
__device__ __forceinline__ float2 cfmac(float2 a, float2 b, float2 c) {
    c.x = fmaf(a.x, b.x, fmaf(-a.y, b.y, c.x));
    c.y = fmaf(a.x, b.y, fmaf(a.y, b.x, c.y));
    return c;
}

// ---------------------------------------------------------------------------
// Setup: 32 blocks x 64 threads. Gates computed in parallel, matrices built
// column-parallel, 7x7 grid eval, exact DFT, duplicated/sign-baked pack.
// ---------------------------------------------------------------------------
__global__ void setup_kernel(const float* __restrict__ qstyles) {
    const int b = blockIdx.x;
    const int t = threadIdx.x;
    __shared__ float2 shU[16][4];    // u3 entries per gate
    __shared__ float2 shM[4][16];    // block matrices
    __shared__ float sh_ev[49];
    __shared__ float2 tw[7];
    __shared__ float2 sh_c[4][7];

    const float TWO_PI_7 = 6.28318530717958647692f / 7.0f;

    // Phase 0: 16 gates in parallel. gate = blk*4 + j*2 + k
    if (t < 16) {
        const int blk = t >> 2, j = (t >> 1) & 1, k = t & 1;
        const float* p = qstyles + ((((b * 4 + blk) * 2 + j) * 2 + k) * 3);
        float th = p[0], ph = p[1], la = p[2];
        float ct, st, cl, sl, cp, sp, cpl, spl;
        __sincosf(0.5f * th, &st, &ct);
        __sincosf(la, &sl, &cl);
        __sincosf(ph, &sp, &cp);
        __sincosf(ph + la, &spl, &cpl);
        shU[t][0] = make_float2(ct, 0.f);
        shU[t][1] = make_float2(-cl * st, -sl * st);
        shU[t][2] = make_float2(cp * st, sp * st);
        shU[t][3] = make_float2(cpl * ct, spl * ct);
    }
    if (t >= 16 && t < 23) {
        int k = t - 16;
        float sn, cs;
        sincosf(-TWO_PI_7 * (float)k, &sn, &cs);
        tw[k] = make_float2(cs, sn);
    }
    __syncthreads();

    // Phase 1: build matrices, one thread per (blk, column)
    if (t < 16) {
        const int blk = t >> 2, col = t & 3;
        float2 v[4];
        for (int r = 0; r < 4; ++r)
            v[r] = make_float2(r == col ? 1.f : 0.f, 0.f);
        for (int j = 0; j < 2; ++j) {
            {   // wire 0: rows (0,2),(1,3)
                const float2* u = shU[blk * 4 + j * 2 + 0];
                float2 a0 = v[0], a1 = v[1];
                v[0] = cfmac(u[0], a0, cmulc(u[1], v[2]));
                v[2] = cfmac(u[2], a0, cmulc(u[3], v[2]));
                v[1] = cfmac(u[0], a1, cmulc(u[1], v[3]));
                v[3] = cfmac(u[2], a1, cmulc(u[3], v[3]));
            }
            {   // wire 1: rows (0,1),(2,3)
                const float2* u = shU[blk * 4 + j * 2 + 1];
                float2 a0 = v[0], a2 = v[2];
                v[0] = cfmac(u[0], a0, cmulc(u[1], v[1]));
                v[1] = cfmac(u[2], a0, cmulc(u[3], v[1]));
                v[2] = cfmac(u[0], a2, cmulc(u[1], v[3]));
                v[3] = cfmac(u[2], a2, cmulc(u[3], v[3]));
            }
            float2 tmp = v[2]; v[2] = v[3]; v[3] = tmp;  // CNOT
        }
        for (int r = 0; r < 4; ++r) shM[blk][r * 4 + col] = v[r];
    }
    __syncthreads();

    // Phase 2: evaluate ev on the 7x7 grid
    if (t < 49) {
        int j = t / 7, kk = t % 7;
        float x0 = TWO_PI_7 * (float)j, x1 = TWO_PI_7 * (float)kk;
        float ca, sa, cb, sb;
        __sincosf(0.5f * (x0 + x1), &sa, &ca);
        __sincosf(0.5f * (x0 - x1), &sb, &cb);
        float2 d0 = make_float2(ca, -sa), d1 = make_float2(cb, -sb);
        float2 d2 = make_float2(cb, sb), d3 = make_float2(ca, sa);
        float2 s[4];
        for (int i = 0; i < 4; ++i) s[i] = shM[0][i * 4 + 0];
        for (int it = 1; it <= 3; ++it) {
            float2 tv[4];
            tv[0] = cmulc(d0, s[0]); tv[1] = cmulc(d1, s[1]);
            tv[2] = cmulc(d2, s[2]); tv[3] = cmulc(d3, s[3]);
            for (int i = 0; i < 4; ++i) {
                float2 acc = cmulc(shM[it][i * 4 + 0], tv[0]);
                for (int kx = 1; kx < 4; ++kx)
                    acc = cfmac(shM[it][i * 4 + kx], tv[kx], acc);
                s[i] = acc;
            }
        }
        sh_ev[t] = (s[0].x * s[0].x + s[0].y * s[0].y)
                 + (s[1].x * s[1].x + s[1].y * s[1].y)
                 - (s[2].x * s[2].x + s[2].y * s[2].y)
                 - (s[3].x * s[3].x + s[3].y * s[3].y);
    }
    __syncthreads();

    // Phase 3: exact DFT, c_{m,n}, m=0..3, n=-3..3
    if (t < 25) {
        int m, n;
        if (t < 4) { m = 0; n = t; }
        else       { m = 1 + (t - 4) / 7; n = ((t - 4) % 7) - 3; }
        float cr = 0.f, ci = 0.f;
        for (int j = 0; j < 7; ++j)
            for (int kk = 0; kk < 7; ++kk) {
                int r = (m * j + n * kk + 42) % 7;
                float e = sh_ev[j * 7 + kk];
                cr = fmaf(e, tw[r].x, cr);
                ci = fmaf(e, tw[r].y, ci);
            }
        sh_c[m][n + 3] = make_float2(cr * (1.f / 49.f), ci * (1.f / 49.f));
    }
    __syncthreads();

    // Phase 4: duplicated, sign-baked pack
    float* g = g_coef_pk[b];
#define PUT(idx, val) do { g[2 * (idx)] = (val); g[2 * (idx) + 1] = (val); } while (0)
    if (t == 15) { PUT(0, sh_c[0][3].x); PUT(49, 0.f); }
    if (t < 3) {
        int n = t + 1;
        PUT(1 + 2 * t, 2.f * sh_c[0][3 + n].x);
        PUT(2 + 2 * t, -2.f * sh_c[0][3 + n].y);
    }
    if (t >= 3 && t < 6) {
        int m = t - 2;
        int base = 7 + 14 * (m - 1);
        PUT(base + 0, 2.f * sh_c[m][3].x);
        PUT(base + 1, 2.f * sh_c[m][3].y);
    }
    if (t >= 6 && t < 15) {
        int p = t - 6;
        int m = 1 + p / 3, n = 1 + p % 3;
        int q = 7 + 14 * (m - 1) + 2 + 4 * (n - 1);
        float2 cp = sh_c[m][3 + n], cm = sh_c[m][3 - n];
        PUT(q + 0,  2.f * (cp.x + cm.x));   // Pr
        PUT(q + 1, -2.f * (cp.y - cm.y));   // -Mi
        PUT(q + 2,  2.f * (cp.y + cm.y));   // Pi
        PUT(q + 3,  2.f * (cp.x - cm.x));   // Mr
    }
#undef PUT
}

// ---------------------------------------------------------------------------
// Main: f32x2-packed evaluation, 8 elements (4 packed pairs) per thread.
// ---------------------------------------------------------------------------
__device__ __forceinline__ u64 eval_pair(float4 xv, const u64* C) {
    const u64 NEG1 = 0xBF800000BF800000ull;  // {-1.f, -1.f}

    float s0a, c0a, s1a, c1a, s0b, c0b, s1b, c1b;
    __sincosf(xv.x, &s0a, &c0a);
    __sincosf(xv.y, &s1a, &c1a);
    __sincosf(xv.z, &s0b, &c0b);
    __sincosf(xv.w, &s1b, &c1b);

    u64 c0 = pk(c0a, c0b), s0 = pk(s0a, s0b);
    u64 c1 = pk(c1a, c1b), s1 = pk(s1a, s1b);

    // Chebyshev multiples; w-axis sines computed negated.
    u64 tc0 = add2(c0, c0), tc1 = add2(c1, c1);
    u64 cw2 = fma2(tc0, c0, NEG1);
    u64 nsw1 = neg2(s0);
    u64 nsw2 = mul2(tc0, nsw1);
    u64 cw3 = fma2(tc0, cw2, neg2(c0));
    u64 nsw3 = fma2(tc0, nsw2, s0);
    u64 cz2 = fma2(tc1, c1, NEG1);
    u64 sz2 = mul2(tc1, s1);
    u64 cz3 = fma2(tc1, cz2, neg2(c1));
    u64 sz3 = fma2(tc1, sz2, neg2(s1));

    u64 cz[3] = {c1, cz2, cz3};
    u64 sz[3] = {s1, sz2, sz3};
    u64 cw[3] = {c0, cw2, cw3};
    u64 nsw[3] = {nsw1, nsw2, nsw3};

    u64 ev = C[0];
#pragma unroll
    for (int n = 0; n < 3; ++n) {
        ev = fma2(C[1 + 2 * n], cz[n], ev);
        ev = fma2(C[2 + 2 * n], sz[n], ev);
    }
#pragma unroll
    for (int m = 0; m < 3; ++m) {
        const int base = 7 + 14 * m;
        u64 hx = C[base], hy = C[base + 1];
#pragma unroll
        for (int n = 0; n < 3; ++n) {
            const int q = base + 2 + 4 * n;
            hx = fma2(C[q + 0], cz[n], hx);
            hx = fma2(C[q + 1], sz[n], hx);
            hy = fma2(C[q + 2], cz[n], hy);
            hy = fma2(C[q + 3], sz[n], hy);
        }
        ev = fma2(cw[m], hx, ev);
        ev = fma2(nsw[m], hy, ev);
    }
    return ev;
}

__global__ void __launch_bounds__(128) qlayer_kernel(const float* __restrict__ x,
                                                     float* __restrict__ out) {
    const int b = blockIdx.y;

    // Load 50 packed u64 coefficients via 25 LDG.128
    u64 C[50];
    const ulonglong2* gp = reinterpret_cast<const ulonglong2*>(g_coef_pk[b]);
#pragma unroll
    for (int i = 0; i < 25; ++i) {
        ulonglong2 v = gp[i];
        C[2 * i] = v.x;
        C[2 * i + 1] = v.y;
    }

    // 4 float4 loads (8 elements) per thread, block-strided for coalescing.
    const float4* xin = reinterpret_cast<const float4*>(x) + (size_t)b * (HW / 2);
    u64* o = reinterpret_cast<u64*>(out) + (size_t)b * (HW / 2);
    const int base = blockIdx.x * 512 + threadIdx.x;

    float4 xv0 = xin[base + 0 * 128];
    float4 xv1 = xin[base + 1 * 128];
    float4 xv2 = xin[base + 2 * 128];
    float4 xv3 = xin[base + 3 * 128];

    o[base + 0 * 128] = eval_pair(xv0, C);
    o[base + 1 * 128] = eval_pair(xv1, C);
    o[base + 2 * 128] = eval_pair(xv2, C);
    o[base + 3 * 128] = eval_pair(xv3, C);
}

extern "C" void kernel_launch(void* const* d_in, const int* in_sizes, int n_in,
                              void* d_out, int out_size) {
    const float* x  = (const float*)d_in[0];
    const float* qs = (const float*)d_in[1];
    if (n_in >= 2 && in_sizes[0] < in_sizes[1]) {
        x  = (const float*)d_in[1];
        qs = (const float*)d_in[0];
    }

    setup_kernel<<<NB, 64>>>(qs);

    dim3 grid(HW / (2 * 4 * 128), NB);   // (16, 32)
    qlayer_kernel<<<grid, 128>>>(x, (float*)d_out);
}